// round 5
// baseline (speedup 1.0000x reference)
#include <cuda_runtime.h>
#include <cstdint>

// Aggregator: masked mean of sampled neighbor features (GraphSAGE-style).
//  d_in[0] features:      [N, 128] float32
//  d_in[1] neighbor_idx:  [N, 16]  int32  (int64 in reference, downcast by harness)
//  d_in[2] neighbor_mask: [N, 16]  int32  (bool in reference, stored as int32 0/1)
//  d_out   out:           [N, 128] float32
//
// One warp per node; lane l owns float4 columns [4l, 4l+4).
// Warp-uniform vector loads for mask (4x16B) and indices (4x16B); fully
// unrolled predicated gather loop -> MLP ~= active count against the
// L2-resident feature table.

#define S 16
#define D 128

__global__ __launch_bounds__(256) void agg_kernel(
    const float* __restrict__ feat,
    const int* __restrict__ nidx,
    const int* __restrict__ mask,
    float* __restrict__ out,
    int n)
{
    int warp = (int)((blockIdx.x * (unsigned)blockDim.x + threadIdx.x) >> 5);
    int lane = threadIdx.x & 31;
    if (warp >= n) return;

    // ---- 16 int32 mask values as 4x int4 (uniform across warp) ----
    const int4* mp = reinterpret_cast<const int4*>(mask + (size_t)warp * S);
    unsigned nz = 0;
#pragma unroll
    for (int q = 0; q < 4; q++) {
        int4 m = __ldg(mp + q);
        nz |= (unsigned)(m.x != 0) << (4 * q + 0);
        nz |= (unsigned)(m.y != 0) << (4 * q + 1);
        nz |= (unsigned)(m.z != 0) << (4 * q + 2);
        nz |= (unsigned)(m.w != 0) << (4 * q + 3);
    }
    int cnt = __popc(nz);

    // ---- 16 int32 indices as 4x int4 (uniform across warp) ----
    const int4* ip = reinterpret_cast<const int4*>(nidx + (size_t)warp * S);
    int idx[S];
#pragma unroll
    for (int q = 0; q < 4; q++) {
        int4 v = __ldg(ip + q);
        idx[4 * q + 0] = v.x; idx[4 * q + 1] = v.y;
        idx[4 * q + 2] = v.z; idx[4 * q + 3] = v.w;
    }

    // ---- predicated gather-accumulate over 16 sampled neighbors ----
    float4 acc = make_float4(0.f, 0.f, 0.f, 0.f);
#pragma unroll
    for (int j = 0; j < S; j++) {
        // bounds predicate: converts any remaining dtype misread into a
        // finite wrong answer (diagnosable) instead of a crash
        if ((nz & (1u << j)) && (unsigned)idx[j] < (unsigned)n) {
            const float4* row = reinterpret_cast<const float4*>(feat + (size_t)idx[j] * D);
            float4 v = __ldg(row + lane);       // 512B coalesced per warp
            acc.x += v.x; acc.y += v.y; acc.z += v.z; acc.w += v.w;
        }
    }

    float inv = 1.0f / (float)(cnt > 0 ? cnt : 1);
    acc.x *= inv; acc.y *= inv; acc.z *= inv; acc.w *= inv;

    reinterpret_cast<float4*>(out)[(size_t)warp * (D / 4) + lane] = acc;
}

extern "C" void kernel_launch(void* const* d_in, const int* in_sizes, int n_in,
                              void* d_out, int out_size)
{
    const float* feat = (const float*)d_in[0];
    const int*   nidx = (const int*)d_in[1];
    const int*   mask = (const int*)d_in[2];
    float*       out  = (float*)d_out;

    int n = in_sizes[1] / S;              // 100000 nodes
    int warps_per_block = 256 / 32;       // 8 warps/block
    int blocks = (n + warps_per_block - 1) / warps_per_block;
    agg_kernel<<<blocks, 256>>>(feat, nidx, mask, out, n);
}